// round 16
// baseline (speedup 1.0000x reference)
#include <cuda_runtime.h>
#include <cuda_fp16.h>
#include <cstdint>

#define MAXN 50000
#define MAXE 800000
#define FIN  128
#define FHID 128
#define FOUT2 64
#define SCAN_TILE 4096
#define MAXTILES 32

// ---------------- scratch (device globals; no allocation allowed) ----------
__device__ int    g_deg[MAXN];
__device__ int    g_off[MAXN + 1];
__device__ int    g_cur[MAXN];
__device__ float  g_dis[MAXN];        // rsqrt(deg+1)
__device__ int    g_srcs[MAXE];
__device__ int    g_is64;
__device__ int    g_tsum[MAXTILES];
__device__ __half g_xw[MAXN * FHID];  // x @ W1 (unscaled, fp16)
__device__ __half g_H [MAXN * FHID];  // h = relu(agg1+b1) (fp16)
__device__ __half g_hw[MAXN * FOUT2]; // dis ⊙ (h @ W2) (fp16)
// W transposed ([n][k]), fp16 hi/lo packed as uint2 {hi_pair, lo_pair} per k-pair
__device__ uint2 g_Wp1[FHID * FIN / 2];   // 64KB
__device__ uint2 g_Wp2[FOUT2 * FHID / 2]; // 32KB

// ---------------- side stream for fork/join overlap (host-side objects) ----
static cudaStream_t g_side = nullptr;
static cudaEvent_t  g_ev_fork = nullptr, g_ev_join = nullptr;
static struct SideInit {
    SideInit() {
        cudaStreamCreateWithFlags(&g_side, cudaStreamNonBlocking);
        cudaEventCreateWithFlags(&g_ev_fork, cudaEventDisableTiming);
        cudaEventCreateWithFlags(&g_ev_join, cudaEventDisableTiming);
    }
} g_side_init;

// ---------------- helpers ----------------------------------------------------
__device__ __forceinline__ int load_idx(const void* ei, long long pos, int is64) {
    if (is64) return (int)((const long long*)ei)[pos];
    return ((const int*)ei)[pos];
}

__device__ __forceinline__ void mma_fp16(float* d, const uint32_t* a,
                                         uint32_t b0, uint32_t b1) {
    asm volatile(
        "mma.sync.aligned.m16n8k16.row.col.f32.f16.f16.f32 "
        "{%0,%1,%2,%3}, {%4,%5,%6,%7}, {%8,%9}, {%0,%1,%2,%3};"
        : "+f"(d[0]), "+f"(d[1]), "+f"(d[2]), "+f"(d[3])
        : "r"(a[0]), "r"(a[1]), "r"(a[2]), "r"(a[3]), "r"(b0), "r"(b1));
}

// ---------------- W -> packed Wt fp16 hi/lo (main stream, tiny) -------------
__global__ void k_preW(const float* __restrict__ W1, const float* __restrict__ W2) {
    int b = blockIdx.x, tid = threadIdx.x;
    if (b < 64) {                         // W1: 16384 elems, [k=128][n=128]
        int e = b * 256 + tid;
        int k = e >> 7, nn = e & 127;
        float w = W1[e];
        __half h = __float2half_rn(w);
        __half l = __float2half_rn(w - __half2float(h));
        unsigned char* base = (unsigned char*)g_Wp1 + (nn * 64 + (k >> 1)) * 8;
        *(__half*)(base + (k & 1) * 2)     = h;
        *(__half*)(base + 4 + (k & 1) * 2) = l;
    } else {                              // W2: 8192 elems, [k=128][n=64]
        int e = (b - 64) * 256 + tid;
        int k = e >> 6, nn = e & 63;
        float w = W2[e];
        __half h = __float2half_rn(w);
        __half l = __float2half_rn(w - __half2float(h));
        unsigned char* base = (unsigned char*)g_Wp2 + (nn * 64 + (k >> 1)) * 8;
        *(__half*)(base + (k & 1) * 2)     = h;
        *(__half*)(base + 4 + (k & 1) * 2) = l;
    }
}

// ---------------- zero + dtype detection (side stream) ----------------------
__global__ void k_zero_detect(const void* ei, int n) {
    int i = blockIdx.x * blockDim.x + threadIdx.x;
    if (i < n) { g_deg[i] = 0; g_cur[i] = 0; }
    if (blockIdx.x == 0) {
        const long long* p = (const long long*)ei;
        int tid = threadIdx.x;
        int ok = 1;
        #pragma unroll
        for (int j = 0; j < 8; j++) {
            long long v = p[tid * 8 + j];
            if (v < 0 || v >= (long long)n) ok = 0;
        }
        int all_ok = __syncthreads_and(ok);
        if (tid == 0) g_is64 = all_ok;
    }
}

__global__ void k_hist(const void* ei, int E) {
    int e = blockIdx.x * blockDim.x + threadIdx.x;
    if (e >= E) return;
    int is64 = g_is64;
    int col = load_idx(ei, (long long)E + e, is64);
    atomicAdd(&g_deg[col], 1);
}

// ---------------- scan phase 1 ----------------------------------------------
__global__ void k_scan1(int n) {
    __shared__ int wsum[32];
    int tid  = threadIdx.x;
    int lane = tid & 31, wid = tid >> 5;
    int base = blockIdx.x * SCAN_TILE + tid * 4;

    int v[4];
    #pragma unroll
    for (int j = 0; j < 4; j++) {
        int i = base + j;
        if (i < n) {
            int d = g_deg[i];
            v[j] = d;
            g_dis[i] = rsqrtf((float)(d + 1));
        } else v[j] = 0;
    }
    int s = v[0] + v[1] + v[2] + v[3];

    int inc = s;
    #pragma unroll
    for (int d = 1; d < 32; d <<= 1) {
        int t = __shfl_up_sync(0xffffffffu, inc, d);
        if (lane >= d) inc += t;
    }
    if (lane == 31) wsum[wid] = inc;
    __syncthreads();
    if (wid == 0) {
        int w = wsum[lane];
        #pragma unroll
        for (int d = 1; d < 32; d <<= 1) {
            int t = __shfl_up_sync(0xffffffffu, w, d);
            if (lane >= d) w += t;
        }
        wsum[lane] = w;
    }
    __syncthreads();
    int excl = inc - s + (wid > 0 ? wsum[wid - 1] : 0);
    int run = excl;
    #pragma unroll
    for (int j = 0; j < 4; j++) {
        int i = base + j;
        if (i < n) g_off[i] = run;
        run += v[j];
    }
    if (tid == 0) g_tsum[blockIdx.x] = wsum[31];
}

// ---------------- scan phases 2+3 merged ------------------------------------
__global__ void k_scan23(int n, int ntiles) {
    __shared__ int sh_toff[32];
    int tid = threadIdx.x;
    if (tid < 32) {
        int t = (tid < ntiles) ? g_tsum[tid] : 0;
        int inc = t;
        #pragma unroll
        for (int d = 1; d < 32; d <<= 1) {
            int u = __shfl_up_sync(0xffffffffu, inc, d);
            if (tid >= d) inc += u;
        }
        sh_toff[tid] = inc - t;
        if (tid == 31 && blockIdx.x == 0) g_off[n] = inc;
    }
    __syncthreads();
    int i = blockIdx.x * blockDim.x + tid;
    if (i < n) g_off[i] += sh_toff[i >> 12];
}

__global__ void k_scatter(const void* ei, int E) {
    int e = blockIdx.x * blockDim.x + threadIdx.x;
    if (e >= E) return;
    int is64 = g_is64;
    int row = load_idx(ei, e, is64);
    int col = load_idx(ei, (long long)E + e, is64);
    int pos = g_off[col] + atomicAdd(&g_cur[col], 1);
    g_srcs[pos] = row;
}

// ---------------- direct-load HMMA GEMM: Y(fp16) = [dis]*(X @ W[128,FO]) ----
// No SMEM, no syncthreads: A fragments loaded straight from global (each
// element used exactly once), converted inline. W exact fp16 hi/lo: 2 MMAs.
// 256 thr / 8 warps; M-tile 64; warp grid 2(row)x4(col).
// SRC=0: A from fp32 X (cvt). SRC=1: A from fp16 H (raw). SCALE: epilogue dis.
template <int FO, int SRC, int SCALE>
__global__ void __launch_bounds__(256)
k_gemm_dir(const float* __restrict__ X,
           const __half* __restrict__ Xh,
           const uint2* __restrict__ Wp,
           const float* __restrict__ scale, __half* __restrict__ Y, int n) {
    constexpr int NTW = FO / 32;          // n-tiles per warp (4 or 2)
    int tid = threadIdx.x;
    int wid = tid >> 5, lane = tid & 31;
    int wr = wid >> 2, wc = wid & 3;
    int g = lane >> 2, t = lane & 3;
    int row0 = blockIdx.x * 64;

    int  r_lo[2], r_hi[2];
    bool v_lo[2], v_hi[2];
    #pragma unroll
    for (int rg = 0; rg < 2; rg++) {
        r_lo[rg] = row0 + wr * 32 + rg * 16 + g;
        r_hi[rg] = r_lo[rg] + 8;
        v_lo[rg] = r_lo[rg] < n;
        v_hi[rg] = r_hi[rg] < n;
    }

    float acc[2][NTW][4];
    #pragma unroll
    for (int rg = 0; rg < 2; rg++)
        #pragma unroll
        for (int nt = 0; nt < NTW; nt++)
            #pragma unroll
            for (int c = 0; c < 4; c++) acc[rg][nt][c] = 0.f;

    #pragma unroll
    for (int k0 = 0; k0 < 128; k0 += 16) {
        uint32_t a[2][4];
        #pragma unroll
        for (int rg = 0; rg < 2; rg++) {
            if (SRC == 0) {
                const float* plo = X + (size_t)r_lo[rg] * 128 + k0 + 2 * t;
                const float* phi = X + (size_t)r_hi[rg] * 128 + k0 + 2 * t;
                float2 f0 = v_lo[rg] ? *(const float2*)plo       : make_float2(0.f, 0.f);
                float2 f1 = v_hi[rg] ? *(const float2*)phi       : make_float2(0.f, 0.f);
                float2 f2 = v_lo[rg] ? *(const float2*)(plo + 8) : make_float2(0.f, 0.f);
                float2 f3 = v_hi[rg] ? *(const float2*)(phi + 8) : make_float2(0.f, 0.f);
                __half2 h0 = __floats2half2_rn(f0.x, f0.y);
                __half2 h1 = __floats2half2_rn(f1.x, f1.y);
                __half2 h2 = __floats2half2_rn(f2.x, f2.y);
                __half2 h3 = __floats2half2_rn(f3.x, f3.y);
                a[rg][0] = *(uint32_t*)&h0;
                a[rg][1] = *(uint32_t*)&h1;
                a[rg][2] = *(uint32_t*)&h2;
                a[rg][3] = *(uint32_t*)&h3;
            } else {
                const __half* plo = Xh + (size_t)r_lo[rg] * 128 + k0 + 2 * t;
                const __half* phi = Xh + (size_t)r_hi[rg] * 128 + k0 + 2 * t;
                a[rg][0] = v_lo[rg] ? *(const uint32_t*)plo       : 0u;
                a[rg][1] = v_hi[rg] ? *(const uint32_t*)phi       : 0u;
                a[rg][2] = v_lo[rg] ? *(const uint32_t*)(plo + 8) : 0u;
                a[rg][3] = v_hi[rg] ? *(const uint32_t*)(phi + 8) : 0u;
            }
        }
        #pragma unroll
        for (int nt = 0; nt < NTW; nt++) {
            int ncol = wc * (NTW * 8) + nt * 8 + g;
            const uint2* bp = Wp + ncol * 64 + (k0 >> 1) + t;
            uint2 b0 = __ldg(bp);       // {hi pair, lo pair} at k0+2t
            uint2 b1 = __ldg(bp + 4);   // {hi pair, lo pair} at k0+2t+8
            #pragma unroll
            for (int rg = 0; rg < 2; rg++) {
                mma_fp16(acc[rg][nt], a[rg], b0.x, b1.x);
                mma_fp16(acc[rg][nt], a[rg], b0.y, b1.y);
            }
        }
    }

    // epilogue: fp16 output; d0,d1 -> (row, 2t), d2,d3 -> (row+8, 2t)
    #pragma unroll
    for (int rg = 0; rg < 2; rg++) {
        float s0 = 1.f, s1 = 1.f;
        if (SCALE) {
            s0 = v_lo[rg] ? scale[r_lo[rg]] : 0.f;
            s1 = v_hi[rg] ? scale[r_hi[rg]] : 0.f;
        }
        #pragma unroll
        for (int nt = 0; nt < NTW; nt++) {
            int col = wc * (NTW * 8) + nt * 8 + 2 * t;
            if (v_lo[rg]) {
                __half2 o = __floats2half2_rn(acc[rg][nt][0] * s0,
                                              acc[rg][nt][1] * s0);
                *(__half2*)(Y + (size_t)r_lo[rg] * FO + col) = o;
            }
            if (v_hi[rg]) {
                __half2 o = __floats2half2_rn(acc[rg][nt][2] * s1,
                                              acc[rg][nt][3] * s1);
                *(__half2*)(Y + (size_t)r_hi[rg] * FO + col) = o;
            }
        }
    }
}

// ---------------- aggregation: warp per destination node -------------------
// xw fp16 UNscaled: h = relu(di*(sum_j dj*xw_j + di*xw_i) + b) -> fp16
__global__ void k_agg128(const __half* __restrict__ xw, const float* __restrict__ bias,
                         __half* __restrict__ H, int n) {
    int warp = (blockIdx.x * blockDim.x + threadIdx.x) >> 5;
    int lane = threadIdx.x & 31;
    if (warp >= n) return;
    int node = warp;
    int s = g_off[node], e = g_off[node + 1];
    float di = g_dis[node];
    const uint2* xw2 = (const uint2*)xw;   // 4 halves per uint2; 32 per row

    uint2 vsu = xw2[node * 32 + lane];
    float2 vsa = __half22float2(*(__half2*)&vsu.x);
    float2 vsb = __half22float2(*(__half2*)&vsu.y);
    float4 acc;
    acc.x = di * vsa.x; acc.y = di * vsa.y; acc.z = di * vsb.x; acc.w = di * vsb.y;
    int p = s;
    for (; p + 3 < e; p += 4) {
        int s0 = g_srcs[p], s1 = g_srcs[p + 1], s2 = g_srcs[p + 2], s3 = g_srcs[p + 3];
        float w0 = g_dis[s0], w1 = g_dis[s1], w2 = g_dis[s2], w3 = g_dis[s3];
        uint2 u0 = xw2[s0 * 32 + lane];
        uint2 u1 = xw2[s1 * 32 + lane];
        uint2 u2 = xw2[s2 * 32 + lane];
        uint2 u3 = xw2[s3 * 32 + lane];
        float2 a0 = __half22float2(*(__half2*)&u0.x), b0 = __half22float2(*(__half2*)&u0.y);
        float2 a1 = __half22float2(*(__half2*)&u1.x), b1 = __half22float2(*(__half2*)&u1.y);
        float2 a2 = __half22float2(*(__half2*)&u2.x), b2 = __half22float2(*(__half2*)&u2.y);
        float2 a3 = __half22float2(*(__half2*)&u3.x), b3 = __half22float2(*(__half2*)&u3.y);
        acc.x += w0 * a0.x + w1 * a1.x + w2 * a2.x + w3 * a3.x;
        acc.y += w0 * a0.y + w1 * a1.y + w2 * a2.y + w3 * a3.y;
        acc.z += w0 * b0.x + w1 * b1.x + w2 * b2.x + w3 * b3.x;
        acc.w += w0 * b0.y + w1 * b1.y + w2 * b2.y + w3 * b3.y;
    }
    for (; p < e; p++) {
        int s0 = g_srcs[p];
        float w0 = g_dis[s0];
        uint2 u0 = xw2[s0 * 32 + lane];
        float2 a0 = __half22float2(*(__half2*)&u0.x), b0 = __half22float2(*(__half2*)&u0.y);
        acc.x += w0 * a0.x; acc.y += w0 * a0.y;
        acc.z += w0 * b0.x; acc.w += w0 * b0.y;
    }
    float4 bb = ((const float4*)bias)[lane];
    acc.x = fmaxf(di * acc.x + bb.x, 0.f);
    acc.y = fmaxf(di * acc.y + bb.y, 0.f);
    acc.z = fmaxf(di * acc.z + bb.z, 0.f);
    acc.w = fmaxf(di * acc.w + bb.w, 0.f);

    __half2 h0 = __floats2half2_rn(acc.x, acc.y);
    __half2 h1 = __floats2half2_rn(acc.z, acc.w);
    ((uint2*)H)[node * 32 + lane] = make_uint2(*(uint32_t*)&h0, *(uint32_t*)&h1);
}

// hw fp16, pre-scaled by dis: out = di*(sum hw_j + hw_i) + b   (fp32 out)
__global__ void k_agg64(const __half* __restrict__ hw, const float* __restrict__ bias,
                        float* __restrict__ out, int n) {
    int warp = (blockIdx.x * blockDim.x + threadIdx.x) >> 5;
    int lane = threadIdx.x & 31;
    if (warp >= n) return;
    int node = warp;
    int s = g_off[node], e = g_off[node + 1];
    float di = g_dis[node];
    const uint32_t* hw1 = (const uint32_t*)hw;   // 2 halves per uint; 32 per row

    uint32_t vu = hw1[node * 32 + lane];
    float2 acc = __half22float2(*(__half2*)&vu);
    int p = s;
    for (; p + 3 < e; p += 4) {
        int s0 = g_srcs[p], s1 = g_srcs[p + 1], s2 = g_srcs[p + 2], s3 = g_srcs[p + 3];
        uint32_t u0 = hw1[s0 * 32 + lane];
        uint32_t u1 = hw1[s1 * 32 + lane];
        uint32_t u2 = hw1[s2 * 32 + lane];
        uint32_t u3 = hw1[s3 * 32 + lane];
        float2 a0 = __half22float2(*(__half2*)&u0);
        float2 a1 = __half22float2(*(__half2*)&u1);
        float2 a2 = __half22float2(*(__half2*)&u2);
        float2 a3 = __half22float2(*(__half2*)&u3);
        acc.x += a0.x + a1.x + a2.x + a3.x;
        acc.y += a0.y + a1.y + a2.y + a3.y;
    }
    for (; p < e; p++) {
        int s0 = g_srcs[p];
        uint32_t u0 = hw1[s0 * 32 + lane];
        float2 a0 = __half22float2(*(__half2*)&u0);
        acc.x += a0.x; acc.y += a0.y;
    }
    float2 bb = ((const float2*)bias)[lane];
    acc.x = di * acc.x + bb.x;
    acc.y = di * acc.y + bb.y;
    ((float2*)out)[node * 32 + lane] = acc;
}

// ---------------- launch ----------------------------------------------------
extern "C" void kernel_launch(void* const* d_in, const int* in_sizes, int n_in,
                              void* d_out, int out_size) {
    const float* x  = (const float*)d_in[0];
    const void*  ei = d_in[1];
    const float* W1 = (const float*)d_in[2];
    const float* b1 = (const float*)d_in[3];
    const float* W2 = (const float*)d_in[4];
    const float* b2 = (const float*)d_in[5];
    float* out = (float*)d_out;

    int n = in_sizes[0] / FIN;
    int E = in_sizes[1] / 2;
    if (n > MAXN) n = MAXN;
    if (E > MAXE) E = MAXE;
    int ntiles = (n + SCAN_TILE - 1) / SCAN_TILE;
    int nbn = (n + 255) / 256;

    __half *p_xw, *p_H, *p_hw;
    float *p_dis;
    uint2 *p_wp1, *p_wp2;
    cudaGetSymbolAddress((void**)&p_xw,  g_xw);
    cudaGetSymbolAddress((void**)&p_H,   g_H);
    cudaGetSymbolAddress((void**)&p_hw,  g_hw);
    cudaGetSymbolAddress((void**)&p_dis, g_dis);
    cudaGetSymbolAddress((void**)&p_wp1, g_Wp1);
    cudaGetSymbolAddress((void**)&p_wp2, g_Wp2);

    int gemm_blocks = (n + 63) / 64;

    // ---- fork: edge pipeline on side stream, GEMM path on main stream ----
    cudaEventRecord(g_ev_fork, 0);
    cudaStreamWaitEvent(g_side, g_ev_fork, 0);

    // side stream: CSR build (independent of gemm1)
    k_zero_detect<<<nbn, 256, 0, g_side>>>(ei, n);
    k_hist<<<(E + 255) / 256, 256, 0, g_side>>>(ei, E);
    k_scan1<<<ntiles, 1024, 0, g_side>>>(n);
    k_scan23<<<(n + 255) / 256, 256, 0, g_side>>>(n, ntiles);
    k_scatter<<<(E + 255) / 256, 256, 0, g_side>>>(ei, E);
    cudaEventRecord(g_ev_join, g_side);

    // main stream: W pack + layer-1 GEMM (direct-load, fp16 out, unscaled)
    k_preW<<<96, 256>>>(W1, W2);
    k_gemm_dir<128, 0, 0><<<gemm_blocks, 256>>>(
        x, nullptr, p_wp1, nullptr, p_xw, n);

    // join, then the serial tail
    cudaStreamWaitEvent(0, g_ev_join, 0);
    k_agg128<<<(n + 7) / 8, 256>>>(p_xw, b1, p_H, n);
    k_gemm_dir<64, 1, 1><<<gemm_blocks, 256>>>(
        nullptr, p_H, p_wp2, p_dis, p_hw, n);
    k_agg64<<<(n + 7) / 8, 256>>>(p_hw, b2, out, n);
}

// round 17
// speedup vs baseline: 1.6796x; 1.6796x over previous
#include <cuda_runtime.h>
#include <cuda_fp16.h>
#include <cstdint>

#define MAXN 50000
#define MAXE 800000
#define FIN  128
#define FHID 128
#define FOUT2 64
#define SCAN_TILE 4096
#define MAXTILES 32

// ---------------- scratch (device globals; no allocation allowed) ----------
__device__ int    g_deg[MAXN];
__device__ int    g_off[MAXN + 1];
__device__ int    g_cur[MAXN];
__device__ float  g_dis[MAXN];        // rsqrt(deg+1)
__device__ int    g_srcs[MAXE];
__device__ int    g_is64;
__device__ int    g_tsum[MAXTILES];
__device__ __half g_xw[MAXN * FHID];  // x @ W1 (unscaled, fp16)
__device__ __half g_H [MAXN * FHID];  // h = relu(agg1+b1) (fp16)
__device__ __half g_hw[MAXN * FOUT2]; // dis ⊙ (h @ W2) (fp16)
// W transposed ([n][k]), fp16 hi/lo packed as uint2 {hi_pair, lo_pair} per k-pair
__device__ uint2 g_Wp1[FHID * FIN / 2];   // 64KB
__device__ uint2 g_Wp2[FOUT2 * FHID / 2]; // 32KB

// ---------------- side stream for fork/join overlap (host-side objects) ----
static cudaStream_t g_side = nullptr;
static cudaEvent_t  g_ev_fork = nullptr, g_ev_join = nullptr;
static struct SideInit {
    SideInit() {
        cudaStreamCreateWithFlags(&g_side, cudaStreamNonBlocking);
        cudaEventCreateWithFlags(&g_ev_fork, cudaEventDisableTiming);
        cudaEventCreateWithFlags(&g_ev_join, cudaEventDisableTiming);
    }
} g_side_init;

// ---------------- helpers ----------------------------------------------------
__device__ __forceinline__ int load_idx(const void* ei, long long pos, int is64) {
    if (is64) return (int)((const long long*)ei)[pos];
    return ((const int*)ei)[pos];
}

__device__ __forceinline__ void mma_fp16(float* d, const uint32_t* a,
                                         uint32_t b0, uint32_t b1) {
    asm volatile(
        "mma.sync.aligned.m16n8k16.row.col.f32.f16.f16.f32 "
        "{%0,%1,%2,%3}, {%4,%5,%6,%7}, {%8,%9}, {%0,%1,%2,%3};"
        : "+f"(d[0]), "+f"(d[1]), "+f"(d[2]), "+f"(d[3])
        : "r"(a[0]), "r"(a[1]), "r"(a[2]), "r"(a[3]), "r"(b0), "r"(b1));
}

__device__ __forceinline__ void ldsm_x4(uint32_t* r, uint32_t saddr) {
    asm volatile("ldmatrix.sync.aligned.m8n8.x4.shared.b16 {%0,%1,%2,%3}, [%4];"
        : "=r"(r[0]), "=r"(r[1]), "=r"(r[2]), "=r"(r[3]) : "r"(saddr));
}

// ---------------- W -> packed Wt fp16 hi/lo (main stream, tiny) -------------
__global__ void k_preW(const float* __restrict__ W1, const float* __restrict__ W2) {
    int b = blockIdx.x, tid = threadIdx.x;
    if (b < 64) {                         // W1: 16384 elems, [k=128][n=128]
        int e = b * 256 + tid;
        int k = e >> 7, nn = e & 127;
        float w = W1[e];
        __half h = __float2half_rn(w);
        __half l = __float2half_rn(w - __half2float(h));
        unsigned char* base = (unsigned char*)g_Wp1 + (nn * 64 + (k >> 1)) * 8;
        *(__half*)(base + (k & 1) * 2)     = h;
        *(__half*)(base + 4 + (k & 1) * 2) = l;
    } else {                              // W2: 8192 elems, [k=128][n=64]
        int e = (b - 64) * 256 + tid;
        int k = e >> 6, nn = e & 63;
        float w = W2[e];
        __half h = __float2half_rn(w);
        __half l = __float2half_rn(w - __half2float(h));
        unsigned char* base = (unsigned char*)g_Wp2 + (nn * 64 + (k >> 1)) * 8;
        *(__half*)(base + (k & 1) * 2)     = h;
        *(__half*)(base + 4 + (k & 1) * 2) = l;
    }
}

// ---------------- zero + dtype detection (side stream) ----------------------
__global__ void k_zero_detect(const void* ei, int n) {
    int i = blockIdx.x * blockDim.x + threadIdx.x;
    if (i < n) { g_deg[i] = 0; g_cur[i] = 0; }
    if (blockIdx.x == 0) {
        const long long* p = (const long long*)ei;
        int tid = threadIdx.x;
        int ok = 1;
        #pragma unroll
        for (int j = 0; j < 8; j++) {
            long long v = p[tid * 8 + j];
            if (v < 0 || v >= (long long)n) ok = 0;
        }
        int all_ok = __syncthreads_and(ok);
        if (tid == 0) g_is64 = all_ok;
    }
}

__global__ void k_hist(const void* ei, int E) {
    int e = blockIdx.x * blockDim.x + threadIdx.x;
    if (e >= E) return;
    int is64 = g_is64;
    int col = load_idx(ei, (long long)E + e, is64);
    atomicAdd(&g_deg[col], 1);
}

// ---------------- scan phase 1 ----------------------------------------------
__global__ void k_scan1(int n) {
    __shared__ int wsum[32];
    int tid  = threadIdx.x;
    int lane = tid & 31, wid = tid >> 5;
    int base = blockIdx.x * SCAN_TILE + tid * 4;

    int v[4];
    #pragma unroll
    for (int j = 0; j < 4; j++) {
        int i = base + j;
        if (i < n) {
            int d = g_deg[i];
            v[j] = d;
            g_dis[i] = rsqrtf((float)(d + 1));
        } else v[j] = 0;
    }
    int s = v[0] + v[1] + v[2] + v[3];

    int inc = s;
    #pragma unroll
    for (int d = 1; d < 32; d <<= 1) {
        int t = __shfl_up_sync(0xffffffffu, inc, d);
        if (lane >= d) inc += t;
    }
    if (lane == 31) wsum[wid] = inc;
    __syncthreads();
    if (wid == 0) {
        int w = wsum[lane];
        #pragma unroll
        for (int d = 1; d < 32; d <<= 1) {
            int t = __shfl_up_sync(0xffffffffu, w, d);
            if (lane >= d) w += t;
        }
        wsum[lane] = w;
    }
    __syncthreads();
    int excl = inc - s + (wid > 0 ? wsum[wid - 1] : 0);
    int run = excl;
    #pragma unroll
    for (int j = 0; j < 4; j++) {
        int i = base + j;
        if (i < n) g_off[i] = run;
        run += v[j];
    }
    if (tid == 0) g_tsum[blockIdx.x] = wsum[31];
}

// ---------------- scan phases 2+3 merged ------------------------------------
__global__ void k_scan23(int n, int ntiles) {
    __shared__ int sh_toff[32];
    int tid = threadIdx.x;
    if (tid < 32) {
        int t = (tid < ntiles) ? g_tsum[tid] : 0;
        int inc = t;
        #pragma unroll
        for (int d = 1; d < 32; d <<= 1) {
            int u = __shfl_up_sync(0xffffffffu, inc, d);
            if (tid >= d) inc += u;
        }
        sh_toff[tid] = inc - t;
        if (tid == 31 && blockIdx.x == 0) g_off[n] = inc;
    }
    __syncthreads();
    int i = blockIdx.x * blockDim.x + tid;
    if (i < n) g_off[i] += sh_toff[i >> 12];
}

__global__ void k_scatter(const void* ei, int E) {
    int e = blockIdx.x * blockDim.x + threadIdx.x;
    if (e >= E) return;
    int is64 = g_is64;
    int row = load_idx(ei, e, is64);
    int col = load_idx(ei, (long long)E + e, is64);
    int pos = g_off[col] + atomicAdd(&g_cur[col], 1);
    g_srcs[pos] = row;
}

// ---------------- HMMA GEMM: Y(fp16) = [scale[r]] * (X[n,128] @ W[128,FO]) --
// x single fp16 + W exact fp16 hi/lo split: 2 MMAs per tile. SMEM-staged A,
// ldmatrix fragments. 256 thr / 8 warps; M-tile 64; warp grid 2(row)x4(col).
// SRC=0: A from fp32 X (convert). SRC=1: A from fp16 H. SCALE: epilogue dis.
template <int FO, int SRC, int OCC, int SCALE>
__global__ void __launch_bounds__(256, OCC)
k_gemm_mma(const float* __restrict__ X,
           const __half* __restrict__ Xh,
           const uint2* __restrict__ Wp,
           const float* __restrict__ scale, __half* __restrict__ Y, int n) {
    constexpr int NTW = FO / 32;          // n-tiles per warp (4 or 2)
    constexpr int SAS = 136;              // padded fp16 row stride (17 x 16B)
    extern __shared__ char smem[];
    __half* sA = (__half*)smem;           // 64 * SAS fp16

    int tid = threadIdx.x;
    int row0 = blockIdx.x * 64;

    if (SRC == 0) {
        const float4* X4 = (const float4*)X;
        for (int i = tid; i < 64 * 32; i += 256) {
            int r = i >> 5, c = i & 31;
            int gr = row0 + r;
            float4 f = (gr < n) ? X4[(size_t)gr * 32 + c]
                                : make_float4(0.f, 0.f, 0.f, 0.f);
            __half2 h0 = __floats2half2_rn(f.x, f.y);
            __half2 h1 = __floats2half2_rn(f.z, f.w);
            *(uint2*)(sA + r * SAS + c * 4) = make_uint2(*(uint32_t*)&h0, *(uint32_t*)&h1);
        }
    } else {
        const uint4* H4 = (const uint4*)Xh;
        const uint4 z4 = make_uint4(0, 0, 0, 0);
        for (int i = tid; i < 64 * 16; i += 256) {
            int r = i >> 4, c = i & 15;
            int gr = row0 + r;
            uint4 hv = (gr < n) ? H4[(size_t)gr * 16 + c] : z4;
            *(uint4*)((char*)sA + r * 272 + c * 16) = hv;
        }
    }
    __syncthreads();

    int wid = tid >> 5, lane = tid & 31;
    int wr = wid >> 2, wc = wid & 3;
    int g = lane >> 2, t = lane & 3;
    int lrow = lane & 15, lcol = (lane >> 4) << 3;
    uint32_t a_base = (uint32_t)__cvta_generic_to_shared(sA);
    uint32_t a_addr[2];
    #pragma unroll
    for (int rg = 0; rg < 2; rg++)
        a_addr[rg] = a_base + (uint32_t)(((wr * 32 + rg * 16 + lrow) * SAS + lcol) * 2);

    float acc[2][NTW][4];
    #pragma unroll
    for (int rg = 0; rg < 2; rg++)
        #pragma unroll
        for (int nt = 0; nt < NTW; nt++)
            #pragma unroll
            for (int c = 0; c < 4; c++) acc[rg][nt][c] = 0.f;

    #pragma unroll
    for (int k0 = 0; k0 < 128; k0 += 16) {
        uint32_t a[2][4];
        #pragma unroll
        for (int rg = 0; rg < 2; rg++)
            ldsm_x4(a[rg], a_addr[rg] + k0 * 2);
        #pragma unroll
        for (int nt = 0; nt < NTW; nt++) {
            int ncol = wc * (NTW * 8) + nt * 8 + g;
            const uint2* bp = Wp + ncol * 64 + (k0 >> 1) + t;
            uint2 b0 = __ldg(bp);       // {hi pair, lo pair} at k0+2t
            uint2 b1 = __ldg(bp + 4);   // {hi pair, lo pair} at k0+2t+8
            #pragma unroll
            for (int rg = 0; rg < 2; rg++) {
                mma_fp16(acc[rg][nt], a[rg], b0.x, b1.x);
                mma_fp16(acc[rg][nt], a[rg], b0.y, b1.y);
            }
        }
    }

    // epilogue: fp16 output; d0,d1 -> (row, 2t), d2,d3 -> (row+8, 2t)
    #pragma unroll
    for (int rg = 0; rg < 2; rg++) {
        int r_lo = row0 + wr * 32 + rg * 16 + g;
        int r_hi = r_lo + 8;
        float s0 = 1.f, s1 = 1.f;
        if (SCALE) {
            s0 = (r_lo < n) ? scale[r_lo] : 0.f;
            s1 = (r_hi < n) ? scale[r_hi] : 0.f;
        }
        #pragma unroll
        for (int nt = 0; nt < NTW; nt++) {
            int col = wc * (NTW * 8) + nt * 8 + 2 * t;
            if (r_lo < n) {
                __half2 o = __floats2half2_rn(acc[rg][nt][0] * s0,
                                              acc[rg][nt][1] * s0);
                *(__half2*)(Y + (size_t)r_lo * FO + col) = o;
            }
            if (r_hi < n) {
                __half2 o = __floats2half2_rn(acc[rg][nt][2] * s1,
                                              acc[rg][nt][3] * s1);
                *(__half2*)(Y + (size_t)r_hi * FO + col) = o;
            }
        }
    }
}

// ---------------- aggregation: warp per destination node -------------------
// xw fp16 UNscaled: h = relu(di*(sum_j dj*xw_j + di*xw_i) + b) -> fp16
// 8-wide unroll: indices+weights first, then 8 gathers in flight.
__global__ void k_agg128(const __half* __restrict__ xw, const float* __restrict__ bias,
                         __half* __restrict__ H, int n) {
    int warp = (blockIdx.x * blockDim.x + threadIdx.x) >> 5;
    int lane = threadIdx.x & 31;
    if (warp >= n) return;
    int node = warp;
    int s = g_off[node], e = g_off[node + 1];
    float di = g_dis[node];
    const uint2* xw2 = (const uint2*)xw;

    uint2 vsu = xw2[node * 32 + lane];
    float2 vsa = __half22float2(*(__half2*)&vsu.x);
    float2 vsb = __half22float2(*(__half2*)&vsu.y);
    float4 acc;
    acc.x = di * vsa.x; acc.y = di * vsa.y; acc.z = di * vsb.x; acc.w = di * vsb.y;
    int p = s;
    for (; p + 7 < e; p += 8) {
        int   si[8];
        float wi[8];
        uint2 ui[8];
        #pragma unroll
        for (int j = 0; j < 8; j++) si[j] = g_srcs[p + j];
        #pragma unroll
        for (int j = 0; j < 8; j++) wi[j] = g_dis[si[j]];
        #pragma unroll
        for (int j = 0; j < 8; j++) ui[j] = xw2[si[j] * 32 + lane];
        #pragma unroll
        for (int j = 0; j < 8; j++) {
            float2 a = __half22float2(*(__half2*)&ui[j].x);
            float2 b = __half22float2(*(__half2*)&ui[j].y);
            acc.x += wi[j] * a.x; acc.y += wi[j] * a.y;
            acc.z += wi[j] * b.x; acc.w += wi[j] * b.y;
        }
    }
    for (; p < e; p++) {
        int s0 = g_srcs[p];
        float w0 = g_dis[s0];
        uint2 u0 = xw2[s0 * 32 + lane];
        float2 a0 = __half22float2(*(__half2*)&u0.x), b0 = __half22float2(*(__half2*)&u0.y);
        acc.x += w0 * a0.x; acc.y += w0 * a0.y;
        acc.z += w0 * b0.x; acc.w += w0 * b0.y;
    }
    float4 bb = ((const float4*)bias)[lane];
    acc.x = fmaxf(di * acc.x + bb.x, 0.f);
    acc.y = fmaxf(di * acc.y + bb.y, 0.f);
    acc.z = fmaxf(di * acc.z + bb.z, 0.f);
    acc.w = fmaxf(di * acc.w + bb.w, 0.f);

    __half2 h0 = __floats2half2_rn(acc.x, acc.y);
    __half2 h1 = __floats2half2_rn(acc.z, acc.w);
    ((uint2*)H)[node * 32 + lane] = make_uint2(*(uint32_t*)&h0, *(uint32_t*)&h1);
}

// hw fp16, pre-scaled by dis: out = di*(sum hw_j + hw_i) + b   (fp32 out)
__global__ void k_agg64(const __half* __restrict__ hw, const float* __restrict__ bias,
                        float* __restrict__ out, int n) {
    int warp = (blockIdx.x * blockDim.x + threadIdx.x) >> 5;
    int lane = threadIdx.x & 31;
    if (warp >= n) return;
    int node = warp;
    int s = g_off[node], e = g_off[node + 1];
    float di = g_dis[node];
    const uint32_t* hw1 = (const uint32_t*)hw;

    uint32_t vu = hw1[node * 32 + lane];
    float2 acc = __half22float2(*(__half2*)&vu);
    int p = s;
    for (; p + 7 < e; p += 8) {
        int      si[8];
        uint32_t ui[8];
        #pragma unroll
        for (int j = 0; j < 8; j++) si[j] = g_srcs[p + j];
        #pragma unroll
        for (int j = 0; j < 8; j++) ui[j] = hw1[si[j] * 32 + lane];
        #pragma unroll
        for (int j = 0; j < 8; j++) {
            float2 a = __half22float2(*(__half2*)&ui[j]);
            acc.x += a.x; acc.y += a.y;
        }
    }
    for (; p < e; p++) {
        int s0 = g_srcs[p];
        uint32_t u0 = hw1[s0 * 32 + lane];
        float2 a0 = __half22float2(*(__half2*)&u0);
        acc.x += a0.x; acc.y += a0.y;
    }
    float2 bb = ((const float2*)bias)[lane];
    acc.x = di * acc.x + bb.x;
    acc.y = di * acc.y + bb.y;
    ((float2*)out)[node * 32 + lane] = acc;
}

// ---------------- launch ----------------------------------------------------
extern "C" void kernel_launch(void* const* d_in, const int* in_sizes, int n_in,
                              void* d_out, int out_size) {
    const float* x  = (const float*)d_in[0];
    const void*  ei = d_in[1];
    const float* W1 = (const float*)d_in[2];
    const float* b1 = (const float*)d_in[3];
    const float* W2 = (const float*)d_in[4];
    const float* b2 = (const float*)d_in[5];
    float* out = (float*)d_out;

    int n = in_sizes[0] / FIN;
    int E = in_sizes[1] / 2;
    if (n > MAXN) n = MAXN;
    if (E > MAXE) E = MAXE;
    int ntiles = (n + SCAN_TILE - 1) / SCAN_TILE;
    int nbn = (n + 255) / 256;

    __half *p_xw, *p_H, *p_hw;
    float *p_dis;
    uint2 *p_wp1, *p_wp2;
    cudaGetSymbolAddress((void**)&p_xw,  g_xw);
    cudaGetSymbolAddress((void**)&p_H,   g_H);
    cudaGetSymbolAddress((void**)&p_hw,  g_hw);
    cudaGetSymbolAddress((void**)&p_dis, g_dis);
    cudaGetSymbolAddress((void**)&p_wp1, g_Wp1);
    cudaGetSymbolAddress((void**)&p_wp2, g_Wp2);

    // dynamic SMEM: A fp16: 64 rows * 136 fp16 * 2B = 17408
    size_t shg = (size_t)64 * 136 * 2;
    cudaFuncSetAttribute((const void*)k_gemm_mma<128, 0, 3, 0>,
                         cudaFuncAttributeMaxDynamicSharedMemorySize, (int)shg);
    cudaFuncSetAttribute((const void*)k_gemm_mma<64, 1, 4, 1>,
                         cudaFuncAttributeMaxDynamicSharedMemorySize, (int)shg);

    int gemm_blocks = (n + 63) / 64;

    // ---- fork: edge pipeline on side stream, GEMM path on main stream ----
    cudaEventRecord(g_ev_fork, 0);
    cudaStreamWaitEvent(g_side, g_ev_fork, 0);

    // side stream: CSR build (independent of gemm128)
    k_zero_detect<<<nbn, 256, 0, g_side>>>(ei, n);
    k_hist<<<(E + 255) / 256, 256, 0, g_side>>>(ei, E);
    k_scan1<<<ntiles, 1024, 0, g_side>>>(n);
    k_scan23<<<(n + 255) / 256, 256, 0, g_side>>>(n, ntiles);
    k_scatter<<<(E + 255) / 256, 256, 0, g_side>>>(ei, E);
    cudaEventRecord(g_ev_join, g_side);

    // main stream: W pack + layer-1 GEMM (unscaled epilogue, fp16 out)
    k_preW<<<96, 256>>>(W1, W2);
    k_gemm_mma<128, 0, 3, 0><<<gemm_blocks, 256, shg>>>(
        x, nullptr, p_wp1, nullptr, p_xw, n);

    // join, then the serial tail
    cudaStreamWaitEvent(0, g_ev_join, 0);
    k_agg128<<<(n + 7) / 8, 256>>>(p_xw, b1, p_H, n);
    k_gemm_mma<64, 1, 4, 1><<<gemm_blocks, 256, shg>>>(
        nullptr, p_H, p_wp2, p_dis, p_hw, n);
    k_agg64<<<(n + 7) / 8, 256>>>(p_hw, b2, out, n);
}